// round 1
// baseline (speedup 1.0000x reference)
#include <cuda_runtime.h>

#define NG     2048
#define WIMG   128
#define KTOP   10
#define SPLIT  8
#define GPT    (NG / SPLIT)        // 256 gaussians per thread
#define PPB    32                  // pixels per block (one warp-width)
#define THREADS (PPB * SPLIT)      // 256 threads per block
#define NPIX   (WIMG * WIMG)

// Precomputed per-gaussian params (scratch: __device__ globals, no allocs)
__device__ float4 d_P4[NG];   // (-mean_x, -mean_y, a', b')  with -0.5*log2e folded
__device__ float  d_PC[NG];   // c'
__device__ float4 d_C4[NG];   // (r, g, b, 0)

__global__ void prep_kernel(const float* __restrict__ means,
                            const float* __restrict__ rots,
                            const float* __restrict__ lsc,
                            const float* __restrict__ cols) {
    int g = blockIdx.x * blockDim.x + threadIdx.x;
    if (g >= NG) return;
    float th = rots[g];
    float ct = cosf(th), st = sinf(th);
    float ivx = expf(-2.0f * lsc[2*g + 0]);
    float ivy = expf(-2.0f * lsc[2*g + 1]);
    float a = ct*ct*ivx + st*st*ivy;
    float c = st*st*ivx + ct*ct*ivy;
    float b = ct*st*(ivx - ivy);
    const float L = 1.4426950408889634f;  // log2(e)
    // alpha = exp(-0.5*(a dx^2 + 2b dxdy + c dy^2)) = 2^(a' dx^2 + b' dxdy + c' dy^2)
    d_P4[g] = make_float4(-means[2*g + 0], -means[2*g + 1], -0.5f * L * a, -L * b);
    d_PC[g] = -0.5f * L * c;
    d_C4[g] = make_float4(cols[3*g + 0], cols[3*g + 1], cols[3*g + 2], 0.0f);
}

__device__ __forceinline__ float ex2f(float x) {
    float y;
    asm("ex2.approx.ftz.f32 %0, %1;" : "=f"(y) : "f"(x));
    return y;
}

__global__ void __launch_bounds__(THREADS) render_kernel(float* __restrict__ out) {
    __shared__ float s_al[PPB][SPLIT][KTOP];
    __shared__ int   s_ix[PPB][SPLIT][KTOP];

    const int lane = threadIdx.x & 31;   // pixel within block
    const int sp   = threadIdx.x >> 5;   // split id (gaussian subset)
    const int pix  = blockIdx.x * PPB + lane;
    const float px = (float)(pix & (WIMG - 1)) + 0.5f;
    const float py = (float)(pix >> 7) + 0.5f;

    // register-resident top-K (sorted descending), constant indices only
    float al[KTOP];
    int   ix[KTOP];
#pragma unroll
    for (int k = 0; k < KTOP; k++) { al[k] = 0.0f; ix[k] = 0; }

    const int gbase = sp * GPT;
#pragma unroll 4
    for (int i = 0; i < GPT; i++) {
        int g = gbase + i;
        float4 p = d_P4[g];     // uniform across warp -> broadcast LDG
        float  cc = d_PC[g];
        float dx = px + p.x;
        float dy = py + p.y;
        float q  = p.z * dx * dx + p.w * dx * dy + cc * dy * dy;
        float alpha = ex2f(q);
        if (alpha > al[KTOP - 1]) {
            float va = alpha; int vi = g;
#pragma unroll
            for (int k = 0; k < KTOP; k++) {
                if (va > al[k]) {
                    float tf = al[k]; al[k] = va; va = tf;
                    int   ti = ix[k]; ix[k] = vi; vi = ti;
                }
            }
        }
    }

#pragma unroll
    for (int k = 0; k < KTOP; k++) {
        s_al[lane][sp][k] = al[k];
        s_ix[lane][sp][k] = ix[k];
    }
    __syncthreads();

    if (sp == 0) {
        // 8-way merge of sorted lists; ascending-split scan with strict '>'
        // reproduces top_k's smallest-index-first tie-break.
        int h0 = 0, h1 = 0, h2 = 0, h3 = 0, h4 = 0, h5 = 0, h6 = 0, h7 = 0;
        float T = 1.0f, rr = 0.0f, gg = 0.0f, bb = 0.0f;
#pragma unroll
        for (int k = 0; k < KTOP; k++) {
            float best = s_al[lane][0][h0];
            int   bi   = s_ix[lane][0][h0];
            int   bs   = 0;
            float v;
            v = s_al[lane][1][h1]; if (v > best) { best = v; bi = s_ix[lane][1][h1]; bs = 1; }
            v = s_al[lane][2][h2]; if (v > best) { best = v; bi = s_ix[lane][2][h2]; bs = 2; }
            v = s_al[lane][3][h3]; if (v > best) { best = v; bi = s_ix[lane][3][h3]; bs = 3; }
            v = s_al[lane][4][h4]; if (v > best) { best = v; bi = s_ix[lane][4][h4]; bs = 4; }
            v = s_al[lane][5][h5]; if (v > best) { best = v; bi = s_ix[lane][5][h5]; bs = 5; }
            v = s_al[lane][6][h6]; if (v > best) { best = v; bi = s_ix[lane][6][h6]; bs = 6; }
            v = s_al[lane][7][h7]; if (v > best) { best = v; bi = s_ix[lane][7][h7]; bs = 7; }
            h0 += (bs == 0); h1 += (bs == 1); h2 += (bs == 2); h3 += (bs == 3);
            h4 += (bs == 4); h5 += (bs == 5); h6 += (bs == 6); h7 += (bs == 7);

            float4 col = d_C4[bi];
            float wgt = best * T;
            rr = fmaf(wgt, col.x, rr);
            gg = fmaf(wgt, col.y, gg);
            bb = fmaf(wgt, col.z, bb);
            T *= (1.0f - best);
        }
        out[3 * pix + 0] = rr;
        out[3 * pix + 1] = gg;
        out[3 * pix + 2] = bb;
    }
}

extern "C" void kernel_launch(void* const* d_in, const int* in_sizes, int n_in,
                              void* d_out, int out_size) {
    (void)in_sizes; (void)n_in; (void)out_size;
    const float* means = (const float*)d_in[0];
    const float* rots  = (const float*)d_in[1];
    const float* lsc   = (const float*)d_in[2];
    const float* cols  = (const float*)d_in[3];
    float* out = (float*)d_out;

    prep_kernel<<<(NG + 255) / 256, 256>>>(means, rots, lsc, cols);
    render_kernel<<<NPIX / PPB, THREADS>>>(out);
}

// round 3
// speedup vs baseline: 1.9913x; 1.9913x over previous
#include <cuda_runtime.h>

#define NG     2048
#define WIMG   128
#define KTOP   10
#define TILE   8
#define TPD    (WIMG / TILE)       // 16 tiles per dim
#define NTILES (TPD * TPD)         // 256
#define SPLIT  4                   // list splits per pixel
#define NPIX   (WIMG * WIMG)

// ---- scratch (__device__ globals; no allocations) ----
__device__ float4 d_P4[NG];            // (-mean_x, -mean_y, a', b')  [-0.5*log2e folded]
__device__ float  d_PC[NG];            // c'
__device__ float4 d_C4[NG];            // (r, g, b, 0)
__device__ float  d_R2[NG];            // cull radius^2 (alpha < ~8e-9 outside)
__device__ int    d_list[NTILES * NG]; // per-tile gaussian index lists (ascending g)
__device__ int    d_cnt[NTILES];

__global__ void prep_kernel(const float* __restrict__ means,
                            const float* __restrict__ rots,
                            const float* __restrict__ lsc,
                            const float* __restrict__ cols) {
    int g = blockIdx.x * blockDim.x + threadIdx.x;
    if (g >= NG) return;
    float th = rots[g];
    float ct = cosf(th), st = sinf(th);
    float ls0 = lsc[2*g + 0], ls1 = lsc[2*g + 1];
    float ivx = expf(-2.0f * ls0);
    float ivy = expf(-2.0f * ls1);
    float a = ct*ct*ivx + st*st*ivy;
    float c = st*st*ivx + ct*ct*ivy;
    float b = ct*st*(ivx - ivy);
    const float L = 1.4426950408889634f;  // log2(e)
    // alpha = 2^(a' dx^2 + b' dx dy + c' dy^2)
    d_P4[g] = make_float4(-means[2*g + 0], -means[2*g + 1], -0.5f * L * a, -L * b);
    d_PC[g] = -0.5f * L * c;
    d_C4[g] = make_float4(cols[3*g + 0], cols[3*g + 1], cols[3*g + 2], 0.0f);
    // alpha >= 8e-9 requires |d| <= 6.1 * sigma_max
    float smax = expf(fmaxf(ls0, ls1));
    float r = 6.1f * smax;
    d_R2[g] = r * r;
}

// Deterministic ordered binning: one block per tile, scans gaussians in index
// order, ordered compaction via ballot + warp-count scan.
__global__ void __launch_bounds__(256) bin_kernel() {
    __shared__ int s_wcnt[8];
    __shared__ int s_base;
    const int tile = blockIdx.x;
    const int tid  = threadIdx.x;
    const int wid  = tid >> 5, lid = tid & 31;
    if (tid == 0) s_base = 0;

    const float x0 = (float)((tile & (TPD-1)) * TILE) + 0.5f;
    const float y0 = (float)((tile >> 4) * TILE) + 0.5f;
    const float x1 = x0 + (float)(TILE - 1);
    const float y1 = y0 + (float)(TILE - 1);

    int* lst = d_list + tile * NG;
    for (int base = 0; base < NG; base += 256) {
        int g = base + tid;
        float4 p = d_P4[g];
        float mx = -p.x, my = -p.y;
        float r2 = d_R2[g];
        float cdx = fmaxf(fmaxf(x0 - mx, mx - x1), 0.0f);
        float cdy = fmaxf(fmaxf(y0 - my, my - y1), 0.0f);
        bool hit = (cdx*cdx + cdy*cdy) <= r2;
        unsigned m = __ballot_sync(0xffffffffu, hit);
        if (lid == 0) s_wcnt[wid] = __popc(m);
        __syncthreads();
        int woff = 0;
#pragma unroll
        for (int w = 0; w < 8; w++) woff += (w < wid) ? s_wcnt[w] : 0;
        int pos = s_base + woff + __popc(m & ((1u << lid) - 1u));
        if (hit) lst[pos] = g;
        __syncthreads();
        if (tid == 0) {
            int t = 0;
#pragma unroll
            for (int w = 0; w < 8; w++) t += s_wcnt[w];
            s_base += t;
        }
        __syncthreads();
    }
    if (tid == 0) d_cnt[tile] = s_base;
}

__device__ __forceinline__ float ex2f(float x) {
    float y;
    asm("ex2.approx.ftz.f32 %0, %1;" : "=f"(y) : "f"(x));
    return y;
}

// Block = half-tile (32 pixels) x SPLIT(4) = 128 threads. Grid = 512.
// Full-precision alpha ordering: (alpha_bits u32, index) pairs; alpha in (0,1]
// so bits compare monotonically as unsigned. Strict '>' + ascending-g scan and
// ascending-split merge reproduce top_k's smallest-index-first tie-break.
__global__ void __launch_bounds__(128) render_kernel(float* __restrict__ out) {
    __shared__ unsigned s_al[32][SPLIT * KTOP + 1];  // stride 41 (odd) -> no conflicts
    __shared__ int      s_ix[32][SPLIT * KTOP + 1];

    const int tid  = threadIdx.x;
    const int lane = tid & 31;      // pixel within half-tile
    const int sp   = tid >> 5;      // split id 0..3
    const int tb   = blockIdx.x >> 1;
    const int half = blockIdx.x & 1;
    const int tx = tb & (TPD-1), ty = tb >> 4;
    const int pit = half * 32 + lane;        // pixel-in-tile 0..63
    const int pxi = pit & (TILE-1), pyi = pit >> 3;
    const float px = (float)(tx * TILE + pxi) + 0.5f;
    const float py = (float)(ty * TILE + pyi) + 0.5f;

    const int len   = d_cnt[tb];
    const int chunk = (len + SPLIT - 1) / SPLIT;
    const int s = sp * chunk;
    const int e = min(s + chunk, len);
    const int* __restrict__ lst = d_list + tb * NG;

    unsigned al[KTOP];
    int      ix[KTOP];
#pragma unroll
    for (int k = 0; k < KTOP; k++) { al[k] = 0u; ix[k] = 0; }

#pragma unroll 2
    for (int i = s; i < e; i++) {
        int g = __ldg(lst + i);               // uniform across warp
        float4 p  = d_P4[g];
        float  cc = d_PC[g];
        float dx = px + p.x;
        float dy = py + p.y;
        float t1 = fmaf(p.w, dy, p.z * dx);
        float q  = fmaf(dx, t1, (cc * dy) * dy);
        float alpha = ex2f(q);
        unsigned abits = __float_as_uint(alpha);
        if (abits > al[KTOP - 1]) {
            unsigned va = abits; int vi = g;
#pragma unroll
            for (int k = 0; k < KTOP; k++) {
                bool t = va > al[k];
                unsigned na = t ? al[k] : va;
                int      ni = t ? ix[k] : vi;
                al[k] = t ? va : al[k];
                ix[k] = t ? vi : ix[k];
                va = na; vi = ni;
            }
        }
    }

#pragma unroll
    for (int k = 0; k < KTOP; k++) {
        s_al[lane][sp * KTOP + k] = al[k];
        s_ix[lane][sp * KTOP + k] = ix[k];
    }
    __syncthreads();

    if (tid < 32) {
        int h0 = 0, h1 = 0, h2 = 0, h3 = 0;
        float T = 1.0f, rr = 0.0f, gg = 0.0f, bb = 0.0f;
#pragma unroll
        for (int k = 0; k < KTOP; k++) {
            unsigned best = s_al[lane][0*KTOP + h0]; int bs = 0;
            unsigned v;
            v = s_al[lane][1*KTOP + h1]; if (v > best) { best = v; bs = 1; }
            v = s_al[lane][2*KTOP + h2]; if (v > best) { best = v; bs = 2; }
            v = s_al[lane][3*KTOP + h3]; if (v > best) { best = v; bs = 3; }
            int bi = s_ix[lane][bs * KTOP + ((bs==0)?h0:(bs==1)?h1:(bs==2)?h2:h3)];
            h0 += (bs == 0); h1 += (bs == 1); h2 += (bs == 2); h3 += (bs == 3);

            float alpha = __uint_as_float(best);
            float4 col = d_C4[bi];
            float wgt = alpha * T;
            rr = fmaf(wgt, col.x, rr);
            gg = fmaf(wgt, col.y, gg);
            bb = fmaf(wgt, col.z, bb);
            T *= (1.0f - alpha);
        }
        int pix = (ty * TILE + pyi) * WIMG + tx * TILE + pxi;
        out[3 * pix + 0] = rr;
        out[3 * pix + 1] = gg;
        out[3 * pix + 2] = bb;
    }
}

extern "C" void kernel_launch(void* const* d_in, const int* in_sizes, int n_in,
                              void* d_out, int out_size) {
    (void)in_sizes; (void)n_in; (void)out_size;
    const float* means = (const float*)d_in[0];
    const float* rots  = (const float*)d_in[1];
    const float* lsc   = (const float*)d_in[2];
    const float* cols  = (const float*)d_in[3];
    float* out = (float*)d_out;

    prep_kernel<<<(NG + 255) / 256, 256>>>(means, rots, lsc, cols);
    bin_kernel<<<NTILES, 256>>>();
    render_kernel<<<NTILES * 2, 128>>>(out);
}

// round 5
// speedup vs baseline: 1.9956x; 1.0022x over previous
#include <cuda_runtime.h>

#define NG     2048
#define WIMG   128
#define KTOP   10
#define TILE   8
#define TPD    16
#define NTILES 256
#define SPLIT  4

// ---- scratch (__device__ globals; no allocations) ----
__device__ float4 d_P4[NG];            // (-mean_x, -mean_y, a', b')  [-0.5*log2e folded]
__device__ float  d_PC[NG];            // c'
__device__ float4 d_C4[NG];            // (r, g, b, 0)
__device__ int    d_list[NTILES * NG]; // per-tile gaussian index lists (ascending g)
__device__ int    d_cnt[NTILES];

// One block per tile. R3's verified ballot-compaction structure, but the hit
// test reads RAW inputs (no prep dependency). Blocks 0..7 additionally compute
// the per-gaussian quadratic params (one gaussian per thread) for render.
__global__ void __launch_bounds__(256) bin_prep_kernel(
    const float* __restrict__ means, const float* __restrict__ rots,
    const float* __restrict__ lsc,   const float* __restrict__ cols) {
    __shared__ int s_wcnt[8];
    __shared__ int s_base;
    const int tile = blockIdx.x;
    const int tid  = threadIdx.x;
    const int wid  = tid >> 5, lid = tid & 31;

    // ---- param writes (blocks 0..7 only): exactly R3's prep math ----
    if (blockIdx.x < 8) {
        int g = blockIdx.x * 256 + tid;
        float th = rots[g];
        float ct = cosf(th), st = sinf(th);
        float ls0 = lsc[2*g + 0], ls1 = lsc[2*g + 1];
        float ivx = expf(-2.0f * ls0);
        float ivy = expf(-2.0f * ls1);
        float a = ct*ct*ivx + st*st*ivy;
        float c = st*st*ivx + ct*ct*ivy;
        float b = ct*st*(ivx - ivy);
        const float L = 1.4426950408889634f;   // log2(e)
        // alpha = 2^(a' dx^2 + b' dx dy + c' dy^2)
        d_P4[g] = make_float4(-means[2*g + 0], -means[2*g + 1], -0.5f*L*a, -L*b);
        d_PC[g] = -0.5f * L * c;
        d_C4[g] = make_float4(cols[3*g + 0], cols[3*g + 1], cols[3*g + 2], 0.0f);
    }

    if (tid == 0) s_base = 0;

    const float x0 = (float)((tile & 15) * TILE) + 0.5f;
    const float y0 = (float)((tile >> 4) * TILE) + 0.5f;
    const float x1 = x0 + 7.0f, y1 = y0 + 7.0f;

    int* lst = d_list + tile * NG;
    for (int base = 0; base < NG; base += 256) {
        int g = base + tid;
        // raw-input hit test: alpha >= ~8e-9 requires |d| <= 6.1*sigma_max
        float mx = means[2*g + 0], my = means[2*g + 1];
        float r  = 6.1f * expf(fmaxf(lsc[2*g + 0], lsc[2*g + 1]));
        float cdx = fmaxf(fmaxf(x0 - mx, mx - x1), 0.0f);
        float cdy = fmaxf(fmaxf(y0 - my, my - y1), 0.0f);
        bool hit = (cdx*cdx + cdy*cdy) <= r*r;
        unsigned m = __ballot_sync(0xffffffffu, hit);
        if (lid == 0) s_wcnt[wid] = __popc(m);
        __syncthreads();
        int woff = 0;
#pragma unroll
        for (int w = 0; w < 8; w++) woff += (w < wid) ? s_wcnt[w] : 0;
        int pos = s_base + woff + __popc(m & ((1u << lid) - 1u));
        if (hit) lst[pos] = g;
        __syncthreads();
        if (tid == 0) {
            int t = 0;
#pragma unroll
            for (int w = 0; w < 8; w++) t += s_wcnt[w];
            s_base += t;
        }
        __syncthreads();
    }
    if (tid == 0) d_cnt[tile] = s_base;
}

__device__ __forceinline__ float ex2f(float x) {
    float y;
    asm("ex2.approx.ftz.f32 %0, %1;" : "=f"(y) : "f"(x));
    return y;
}

// R3's verified render, verbatim. Block = half-tile (32 px) x SPLIT(4) = 128
// threads, grid = 512. Full-precision alpha ordering; ascending-g scan and
// ascending-split merge with strict '>' reproduce top_k's tie-break.
__global__ void __launch_bounds__(128) render_kernel(float* __restrict__ out) {
    __shared__ unsigned s_al[32][SPLIT * KTOP + 1];  // stride 41 -> conflict-free
    __shared__ int      s_ix[32][SPLIT * KTOP + 1];

    const int tid  = threadIdx.x;
    const int lane = tid & 31;      // pixel within half-tile
    const int sp   = tid >> 5;      // split id 0..3
    const int tb   = blockIdx.x >> 1;
    const int half = blockIdx.x & 1;
    const int tx = tb & (TPD-1), ty = tb >> 4;
    const int pit = half * 32 + lane;        // pixel-in-tile 0..63
    const int pxi = pit & (TILE-1), pyi = pit >> 3;
    const float px = (float)(tx * TILE + pxi) + 0.5f;
    const float py = (float)(ty * TILE + pyi) + 0.5f;

    const int len   = d_cnt[tb];
    const int chunk = (len + SPLIT - 1) / SPLIT;
    const int s = sp * chunk;
    const int e = min(s + chunk, len);
    const int* __restrict__ lst = d_list + tb * NG;

    unsigned al[KTOP];
    int      ix[KTOP];
#pragma unroll
    for (int k = 0; k < KTOP; k++) { al[k] = 0u; ix[k] = 0; }

#pragma unroll 2
    for (int i = s; i < e; i++) {
        int g = __ldg(lst + i);               // uniform across warp
        float4 p  = d_P4[g];
        float  cc = d_PC[g];
        float dx = px + p.x;
        float dy = py + p.y;
        float t1 = fmaf(p.w, dy, p.z * dx);
        float q  = fmaf(dx, t1, (cc * dy) * dy);
        float alpha = ex2f(q);
        unsigned abits = __float_as_uint(alpha);  // alpha>0 -> monotone as u32
        if (abits > al[KTOP - 1]) {
            unsigned va = abits; int vi = g;
#pragma unroll
            for (int k = 0; k < KTOP; k++) {
                bool t = va > al[k];
                unsigned na = t ? al[k] : va;
                int      ni = t ? ix[k] : vi;
                al[k] = t ? va : al[k];
                ix[k] = t ? vi : ix[k];
                va = na; vi = ni;
            }
        }
    }

#pragma unroll
    for (int k = 0; k < KTOP; k++) {
        s_al[lane][sp * KTOP + k] = al[k];
        s_ix[lane][sp * KTOP + k] = ix[k];
    }
    __syncthreads();

    if (tid < 32) {
        int h0 = 0, h1 = 0, h2 = 0, h3 = 0;
        float T = 1.0f, rr = 0.0f, gg = 0.0f, bb = 0.0f;
#pragma unroll
        for (int k = 0; k < KTOP; k++) {
            unsigned best = s_al[lane][0*KTOP + h0]; int bs = 0;
            unsigned v;
            v = s_al[lane][1*KTOP + h1]; if (v > best) { best = v; bs = 1; }
            v = s_al[lane][2*KTOP + h2]; if (v > best) { best = v; bs = 2; }
            v = s_al[lane][3*KTOP + h3]; if (v > best) { best = v; bs = 3; }
            int bi = s_ix[lane][bs * KTOP + ((bs==0)?h0:(bs==1)?h1:(bs==2)?h2:h3)];
            h0 += (bs == 0); h1 += (bs == 1); h2 += (bs == 2); h3 += (bs == 3);

            float alpha = __uint_as_float(best);
            float4 col = d_C4[bi];
            float wgt = alpha * T;
            rr = fmaf(wgt, col.x, rr);
            gg = fmaf(wgt, col.y, gg);
            bb = fmaf(wgt, col.z, bb);
            T *= (1.0f - alpha);
        }
        int pix = (ty * TILE + pyi) * WIMG + tx * TILE + pxi;
        out[3 * pix + 0] = rr;
        out[3 * pix + 1] = gg;
        out[3 * pix + 2] = bb;
    }
}

extern "C" void kernel_launch(void* const* d_in, const int* in_sizes, int n_in,
                              void* d_out, int out_size) {
    (void)in_sizes; (void)n_in; (void)out_size;
    const float* means = (const float*)d_in[0];
    const float* rots  = (const float*)d_in[1];
    const float* lsc   = (const float*)d_in[2];
    const float* cols  = (const float*)d_in[3];
    float* out = (float*)d_out;

    bin_prep_kernel<<<NTILES, 256>>>(means, rots, lsc, cols);
    render_kernel<<<NTILES * 2, 128>>>(out);
}